// round 4
// baseline (speedup 1.0000x reference)
#include <cuda_runtime.h>
#include <cstdint>

#define N_SEQ   2048
#define D_MODEL 1024
#define ATTN_SCALE 0.125f

// ---------------- scratch ----------------------------------------------------
__device__ float g_x [N_SEQ * D_MODEL];
__device__ float g_Wq[D_MODEL * D_MODEL];
__device__ float g_Wk[D_MODEL * D_MODEL];
__device__ float g_Wv[D_MODEL * D_MODEL];
__device__ float g_Wo[D_MODEL * D_MODEL];
__device__ float g_Q [N_SEQ * D_MODEL];
__device__ float g_K [N_SEQ * D_MODEL];
__device__ float g_V [N_SEQ * D_MODEL];
__device__ float g_Vt[D_MODEL * N_SEQ];
__device__ float g_AO[N_SEQ * D_MODEL];

// ---------------- helpers ----------------------------------------------------
__device__ __forceinline__ uint32_t f2tf(float x) {
    uint32_t y;
    asm("cvt.rna.tf32.f32 %0, %1;" : "=r"(y) : "f"(x));
    return y;
}
__device__ __forceinline__ float rtf(float x) { return __uint_as_float(f2tf(x)); }

__device__ __forceinline__ void mma_tf32(float c[4], const uint32_t a[4], const uint32_t b[2]) {
    asm volatile(
        "mma.sync.aligned.m16n8k8.row.col.f32.tf32.tf32.f32 "
        "{%0,%1,%2,%3}, {%4,%5,%6,%7}, {%8,%9}, {%0,%1,%2,%3};\n"
        : "+f"(c[0]), "+f"(c[1]), "+f"(c[2]), "+f"(c[3])
        : "r"(a[0]), "r"(a[1]), "r"(a[2]), "r"(a[3]), "r"(b[0]), "r"(b[1]));
}
__device__ __forceinline__ void ldsm4(uint32_t r[4], uint32_t addr) {
    asm volatile("ldmatrix.sync.aligned.m8n8.x4.shared.b16 {%0,%1,%2,%3}, [%4];"
                 : "=r"(r[0]), "=r"(r[1]), "=r"(r[2]), "=r"(r[3]) : "r"(addr));
}
#define CP16(dst, src) asm volatile("cp.async.cg.shared.global [%0], [%1], 16;" :: "r"(dst), "l"(src))
#define CPC            asm volatile("cp.async.commit_group;")
#define CPW(n)         asm volatile("cp.async.wait_group %0;" :: "n"(n))

// ---------------- prep: round inputs to tf32 once ---------------------------
__global__ __launch_bounds__(256) void prep_kernel(
    const float4* __restrict__ x,
    const float4* __restrict__ Wq, const float4* __restrict__ Wk,
    const float4* __restrict__ Wv, const float4* __restrict__ Wo) {
    const float4* src; float4* dst; int n4;
    switch (blockIdx.y) {
        case 0:  src = x;  dst = (float4*)g_x;  n4 = 524288; break;
        case 1:  src = Wq; dst = (float4*)g_Wq; n4 = 262144; break;
        case 2:  src = Wk; dst = (float4*)g_Wk; n4 = 262144; break;
        case 3:  src = Wv; dst = (float4*)g_Wv; n4 = 262144; break;
        default: src = Wo; dst = (float4*)g_Wo; n4 = 262144; break;
    }
    int i = blockIdx.x * 256 + threadIdx.x;
    if (i < n4) {
        float4 v = src[i];
        v.x = rtf(v.x); v.y = rtf(v.y); v.z = rtf(v.z); v.w = rtf(v.w);
        dst[i] = v;
    }
}

// ---------------- V transpose ------------------------------------------------
__global__ __launch_bounds__(256) void transposeV_kernel() {
    __shared__ float t[32][33];
    const int tx = threadIdx.x & 31, ty = threadIdx.x >> 5;
    const int bx = blockIdx.x, by = blockIdx.y;
#pragma unroll
    for (int j = 0; j < 4; j++)
        t[ty + j * 8][tx] = g_V[(size_t)(by * 32 + ty + j * 8) * D_MODEL + bx * 32 + tx];
    __syncthreads();
#pragma unroll
    for (int j = 0; j < 4; j++)
        g_Vt[(size_t)(bx * 32 + ty + j * 8) * N_SEQ + by * 32 + tx] = t[tx][ty + j * 8];
}

// ---------------- GEMM (unchanged from R2): C = A @ W^T + bias ---------------
#define GPAD 36
#define GEMM_SMEM (2 * 2 * 128 * GPAD * 4)

template <bool ROUND>
__device__ __forceinline__ void gemm_body(const float* __restrict__ A, const float* __restrict__ W,
                                          const float* __restrict__ bias, float* __restrict__ C) {
    extern __shared__ uint32_t dsm[];
    const uint32_t sb = (uint32_t)__cvta_generic_to_shared(dsm);
    const int tid = threadIdx.x, warp = tid >> 5, lane = tid & 31;
    const int grp = lane >> 2, four = lane & 3;
    const int wm = warp >> 2, wn = warp & 3;
    const int m0 = blockIdx.x * 128, n0 = blockIdx.y * 128;

    float acc[4][4][4];
#pragma unroll
    for (int mi = 0; mi < 4; mi++)
#pragma unroll
        for (int ni = 0; ni < 4; ni++)
#pragma unroll
            for (int j = 0; j < 4; j++) acc[mi][ni][j] = 0.f;

    const int lr = tid >> 3, lc = (tid & 7) << 2;

#pragma unroll 1
    for (int kt = -1; kt < 32; kt++) {
        if (kt < 31) {
            const int b = (kt + 1) & 1, k0 = (kt + 1) * 32;
#pragma unroll
            for (int i = 0; i < 4; i++) {
                int r = lr + i * 32;
                CP16(sb + (b * 4608 + r * GPAD + lc) * 4,
                     A + (size_t)(m0 + r) * D_MODEL + k0 + lc);
                CP16(sb + (9216 + b * 4608 + r * GPAD + lc) * 4,
                     W + (size_t)(n0 + r) * D_MODEL + k0 + lc);
            }
            CPC;
        }
        if (kt < 0) continue;
        if (kt < 31) { CPW(1); } else { CPW(0); }
        __syncthreads();

        const int b = kt & 1;
        const uint32_t abase0 = sb + (b * 4608 + (wm * 64 + (lane & 15)) * GPAD + ((lane >> 4) << 2)) * 4;
        const uint32_t bbase0 = sb + (9216 + b * 4608 +
                         (wn * 32 + ((lane >> 4) << 3) + (lane & 7)) * GPAD + (((lane >> 3) & 1) << 2)) * 4;
#pragma unroll
        for (int kk = 0; kk < 32; kk += 8) {
            uint32_t a[4][4], bb[2][4];
#pragma unroll
            for (int mi = 0; mi < 4; mi++) ldsm4(a[mi], abase0 + (mi * 16 * GPAD + kk) * 4);
#pragma unroll
            for (int p = 0; p < 2; p++)   ldsm4(bb[p], bbase0 + (p * 16 * GPAD + kk) * 4);
#pragma unroll
            for (int mi = 0; mi < 4; mi++)
#pragma unroll
                for (int ni = 0; ni < 4; ni++)
                    mma_tf32(acc[mi][ni], a[mi], &bb[ni >> 1][(ni & 1) << 1]);
        }
        __syncthreads();
    }

#pragma unroll
    for (int mi = 0; mi < 4; mi++) {
        int r = m0 + wm * 64 + mi * 16 + grp;
#pragma unroll
        for (int ni = 0; ni < 4; ni++) {
            int c = n0 + wn * 32 + ni * 8 + (four << 1);
            float b0 = bias[c], b1 = bias[c + 1];
            float2 v0, v1;
            v0.x = acc[mi][ni][0] + b0; v0.y = acc[mi][ni][1] + b1;
            v1.x = acc[mi][ni][2] + b0; v1.y = acc[mi][ni][3] + b1;
            if (ROUND) { v0.x = rtf(v0.x); v0.y = rtf(v0.y); v1.x = rtf(v1.x); v1.y = rtf(v1.y); }
            *(float2*)(C + (size_t)r * D_MODEL + c)       = v0;
            *(float2*)(C + (size_t)(r + 8) * D_MODEL + c) = v1;
        }
    }
}

__global__ __launch_bounds__(256, 2) void qkv_gemm_kernel(
    const float* __restrict__ bq, const float* __restrict__ bk, const float* __restrict__ bv) {
    const float* W; const float* b; float* C;
    if (blockIdx.z == 0)      { W = g_Wq; b = bq; C = g_Q; }
    else if (blockIdx.z == 1) { W = g_Wk; b = bk; C = g_K; }
    else                      { W = g_Wv; b = bv; C = g_V; }
    gemm_body<true>(g_x, W, b, C);
}

__global__ __launch_bounds__(256, 2) void out_gemm_kernel(
    const float* __restrict__ bo, float* __restrict__ out) {
    gemm_body<false>(g_AO, g_Wo, bo, out);
}

// ---------------- attention (double-buffered, swizzled, Q in regs) -----------
// smem byte offsets: K buffers 2x16KB, V buffers 2x16KB, P 32KB = 96KB total.
#define KS0B 0
#define KS1B 16384
#define VS0B 32768
#define VS1B 49152
#define PSB  65536
#define ATTN_SMEM 98304

// swizzled address: 64-word rows, 16B chunks, chunk ^= (row & 7)
__device__ __forceinline__ uint32_t swad(uint32_t base, int row, int chunk) {
    return base + row * 256 + ((chunk ^ (row & 7)) << 4);
}

__global__ __launch_bounds__(256, 2) void attn_kernel(const float* __restrict__ dbias) {
    extern __shared__ char smraw[];
    const uint32_t sb = (uint32_t)__cvta_generic_to_shared(smraw);
    const int h = blockIdx.x, q0 = blockIdx.y * 128;
    const int tid = threadIdx.x, warp = tid >> 5, lane = tid & 31;
    const int grp = lane >> 2, four = lane & 3;
    const int mb = warp * 16;

    const int lr = tid >> 4, lj = tid & 15;            // loader: row, 16B-chunk
    const int rowb0 = ((lane >> 4) << 3) + (lane & 7); // b-frag row base
    const int bcho  = (lane >> 3) & 1;                 // b-frag chunk offset
    const int arow  = mb + (lane & 15);                // a-frag row
    const int acho  = lane >> 4;                       // a-frag chunk offset

    // stage Q tile into P region
#pragma unroll
    for (int i = 0; i < 8; i++) {
        int r = lr + i * 16;
        CP16(swad(sb + PSB, r, lj), g_Q + (size_t)(q0 + r) * D_MODEL + h * 64 + lj * 4);
    }
    CPC;
    // prologue K/V loads for chunks 0 and 1
#pragma unroll
    for (int b = 0; b < 2; b++) {
        const uint32_t kb = sb + (b ? KS1B : KS0B), vb = sb + (b ? VS1B : VS0B);
        const int key0 = b * 64;
#pragma unroll
        for (int i = 0; i < 4; i++) {
            int r = lr + i * 16;
            CP16(swad(kb, r, lj), g_K  + (size_t)(key0 + r) * D_MODEL + h * 64 + lj * 4);
            CP16(swad(vb, r, lj), g_Vt + (size_t)(h * 64 + r) * N_SEQ + key0 + lj * 4);
        }
        CPC;
    }
    CPW(2);
    __syncthreads();

    // Q fragments -> registers (held for all 32 chunks)
    uint32_t qa[8][4];
#pragma unroll
    for (int ks = 0; ks < 8; ks++)
        ldsm4(qa[ks], swad(sb + PSB, arow, ks * 2 + acho));
    __syncthreads();   // all Q reads done before P overwrites the region

    float Of[8][4], Or[8][4];
#pragma unroll
    for (int ni = 0; ni < 8; ni++)
#pragma unroll
        for (int j = 0; j < 4; j++) { Of[ni][j] = 0.f; Or[ni][j] = 0.f; }
    float l0 = 0.f, l1 = 0.f;

    const float* brow0 = dbias + (size_t)(q0 + mb + grp) * N_SEQ;
    const float* brow1 = brow0 + (size_t)8 * N_SEQ;

#pragma unroll 1
    for (int kc = 0; kc < 32; kc++) {
        if (kc < 31) { CPW(1); } else { CPW(0); }
        __syncthreads();                       // chunk kc data visible CTA-wide

        const int key0 = kc * 64;
        const uint32_t kb = sb + ((kc & 1) ? KS1B : KS0B);
        const uint32_t vb = sb + ((kc & 1) ? VS1B : VS0B);

        // QK + softmax, per ni-pair (keeps s at 8 regs; bias LDG overlaps MMAs)
#pragma unroll
        for (int nip = 0; nip < 4; nip++) {
            float s[2][4];
#pragma unroll
            for (int t = 0; t < 2; t++)
#pragma unroll
                for (int j = 0; j < 4; j++) s[t][j] = 0.f;
            const int rb = nip * 16 + rowb0;
#pragma unroll
            for (int ks = 0; ks < 8; ks++) {
                uint32_t bb[4];
                ldsm4(bb, swad(kb, rb, ks * 2 + bcho));
                mma_tf32(s[0], qa[ks], &bb[0]);
                mma_tf32(s[1], qa[ks], &bb[2]);
            }
#pragma unroll
            for (int t = 0; t < 2; t++) {
                const int ni = nip * 2 + t;
                const int c = ni * 8 + (four << 1);
                float2 bA = *(const float2*)(brow0 + key0 + c);
                float2 bB = *(const float2*)(brow1 + key0 + c);
                float p0 = __expf(fmaf(s[t][0], ATTN_SCALE, -bA.x));
                float p1 = __expf(fmaf(s[t][1], ATTN_SCALE, -bA.y));
                float p2 = __expf(fmaf(s[t][2], ATTN_SCALE, -bB.x));
                float p3 = __expf(fmaf(s[t][3], ATTN_SCALE, -bB.y));
                l0 += p0 + p1; l1 += p2 + p3;
                uint2 u0; u0.x = f2tf(p0); u0.y = f2tf(p1);
                uint2 u1; u1.x = f2tf(p2); u1.y = f2tf(p3);
                const int ch = c >> 2, off = (c & 3) * 4;
                const int rA = mb + grp, rB = rA + 8;
                *(uint2*)(smraw + (swad(sb + PSB, rA, ch) - sb) + off) = u0;
                *(uint2*)(smraw + (swad(sb + PSB, rB, ch) - sb) + off) = u1;
            }
        }
        __syncwarp();                          // own-warp P rows visible

        // Or += P @ V
#pragma unroll
        for (int ks = 0; ks < 8; ks++) {
            uint32_t a[4], bb[4][4];
            ldsm4(a, swad(sb + PSB, arow, ks * 2 + acho));
#pragma unroll
            for (int p = 0; p < 4; p++)
                ldsm4(bb[p], swad(vb, p * 16 + rowb0, ks * 2 + bcho));
#pragma unroll
            for (int ni = 0; ni < 8; ni++)
                mma_tf32(Or[ni], a, &bb[ni >> 1][(ni & 1) << 1]);
        }
        __syncthreads();                       // all warps done with this buffer

        // prefetch chunk kc+2 into the buffer just freed
        if (kc < 30) {
            const int nk0 = key0 + 128;
#pragma unroll
            for (int i = 0; i < 4; i++) {
                int r = lr + i * 16;
                CP16(swad(kb, r, lj), g_K  + (size_t)(nk0 + r) * D_MODEL + h * 64 + lj * 4);
                CP16(swad(vb, r, lj), g_Vt + (size_t)(h * 64 + r) * N_SEQ + nk0 + lj * 4);
            }
            CPC;
        }

        // 256-key block boundary: normalize & accumulate
        if ((kc & 3) == 3) {
            float L0 = l0, L1 = l1;
            L0 += __shfl_xor_sync(0xffffffffu, L0, 1);
            L0 += __shfl_xor_sync(0xffffffffu, L0, 2);
            L1 += __shfl_xor_sync(0xffffffffu, L1, 1);
            L1 += __shfl_xor_sync(0xffffffffu, L1, 2);
            float i0 = 1.0f / L0, i1 = 1.0f / L1;
#pragma unroll
            for (int ni = 0; ni < 8; ni++) {
                Of[ni][0] += Or[ni][0] * i0;
                Of[ni][1] += Or[ni][1] * i0;
                Of[ni][2] += Or[ni][2] * i1;
                Of[ni][3] += Or[ni][3] * i1;
                Or[ni][0] = Or[ni][1] = Or[ni][2] = Or[ni][3] = 0.f;
            }
            l0 = l1 = 0.f;
        }
    }

    const float r8 = 1.0f / (8.0f + 1e-8f);
#pragma unroll
    for (int ni = 0; ni < 8; ni++) {
        int c = h * 64 + ni * 8 + (four << 1);
        float2 v0, v1;
        v0.x = rtf(Of[ni][0] * r8); v0.y = rtf(Of[ni][1] * r8);
        v1.x = rtf(Of[ni][2] * r8); v1.y = rtf(Of[ni][3] * r8);
        *(float2*)(g_AO + (size_t)(q0 + mb + grp) * D_MODEL + c)     = v0;
        *(float2*)(g_AO + (size_t)(q0 + mb + grp + 8) * D_MODEL + c) = v1;
    }
}

// ---------------- launch -----------------------------------------------------
extern "C" void kernel_launch(void* const* d_in, const int* in_sizes, int n_in,
                              void* d_out, int out_size) {
    const float* x  = (const float*)d_in[0];
    const float* db = (const float*)d_in[1];
    const float* Wq = (const float*)d_in[2];
    const float* bq = (const float*)d_in[3];
    const float* Wk = (const float*)d_in[4];
    const float* bk = (const float*)d_in[5];
    const float* Wv = (const float*)d_in[6];
    const float* bv = (const float*)d_in[7];
    const float* Wo = (const float*)d_in[8];
    const float* bo = (const float*)d_in[9];
    float* out = (float*)d_out;

    cudaFuncSetAttribute(qkv_gemm_kernel, cudaFuncAttributeMaxDynamicSharedMemorySize, GEMM_SMEM);
    cudaFuncSetAttribute(out_gemm_kernel, cudaFuncAttributeMaxDynamicSharedMemorySize, GEMM_SMEM);
    cudaFuncSetAttribute(attn_kernel,     cudaFuncAttributeMaxDynamicSharedMemorySize, ATTN_SMEM);

    prep_kernel<<<dim3(2048, 5), 256>>>((const float4*)x, (const float4*)Wq,
                                        (const float4*)Wk, (const float4*)Wv,
                                        (const float4*)Wo);
    qkv_gemm_kernel<<<dim3(16, 8, 3), 256, GEMM_SMEM>>>(bq, bk, bv);
    transposeV_kernel<<<dim3(32, 64), 256>>>();
    attn_kernel<<<dim3(16, 16), 256, ATTN_SMEM>>>(db);
    out_gemm_kernel<<<dim3(16, 8), 256, GEMM_SMEM>>>(bo, out);
}

// round 6
// speedup vs baseline: 1.0809x; 1.0809x over previous
#include <cuda_runtime.h>
#include <cstdint>

#define N_SEQ   2048
#define D_MODEL 1024
#define ATTN_SCALE 0.125f

// ---------------- scratch ----------------------------------------------------
__device__ float g_x [N_SEQ * D_MODEL];
__device__ float g_Wq[D_MODEL * D_MODEL];
__device__ float g_Wk[D_MODEL * D_MODEL];
__device__ float g_Wv[D_MODEL * D_MODEL];
__device__ float g_Wo[D_MODEL * D_MODEL];
__device__ float g_Q [N_SEQ * D_MODEL];
__device__ float g_K [N_SEQ * D_MODEL];
__device__ float g_V [N_SEQ * D_MODEL];
__device__ float g_Vt[D_MODEL * N_SEQ];
__device__ float g_AO[N_SEQ * D_MODEL];

// ---------------- helpers ----------------------------------------------------
__device__ __forceinline__ uint32_t f2tf(float x) {
    uint32_t y;
    asm("cvt.rna.tf32.f32 %0, %1;" : "=r"(y) : "f"(x));
    return y;
}
__device__ __forceinline__ float rtf(float x) { return __uint_as_float(f2tf(x)); }

__device__ __forceinline__ void mma_tf32(float c[4], const uint32_t a[4], const uint32_t b[2]) {
    asm volatile(
        "mma.sync.aligned.m16n8k8.row.col.f32.tf32.tf32.f32 "
        "{%0,%1,%2,%3}, {%4,%5,%6,%7}, {%8,%9}, {%0,%1,%2,%3};\n"
        : "+f"(c[0]), "+f"(c[1]), "+f"(c[2]), "+f"(c[3])
        : "r"(a[0]), "r"(a[1]), "r"(a[2]), "r"(a[3]), "r"(b[0]), "r"(b[1]));
}
__device__ __forceinline__ void ldsm4(uint32_t r[4], uint32_t addr) {
    asm volatile("ldmatrix.sync.aligned.m8n8.x4.shared.b16 {%0,%1,%2,%3}, [%4];"
                 : "=r"(r[0]), "=r"(r[1]), "=r"(r[2]), "=r"(r[3]) : "r"(addr));
}
#define CP16(dst, src) asm volatile("cp.async.cg.shared.global [%0], [%1], 16;" :: "r"(dst), "l"(src))
#define CPC            asm volatile("cp.async.commit_group;")
#define CPW(n)         asm volatile("cp.async.wait_group %0;" :: "n"(n))

// ---------------- prep: round inputs to tf32 once ---------------------------
__global__ __launch_bounds__(256) void prep_kernel(
    const float4* __restrict__ x,
    const float4* __restrict__ Wq, const float4* __restrict__ Wk,
    const float4* __restrict__ Wv, const float4* __restrict__ Wo) {
    const float4* src; float4* dst; int n4;
    switch (blockIdx.y) {
        case 0:  src = x;  dst = (float4*)g_x;  n4 = 524288; break;
        case 1:  src = Wq; dst = (float4*)g_Wq; n4 = 262144; break;
        case 2:  src = Wk; dst = (float4*)g_Wk; n4 = 262144; break;
        case 3:  src = Wv; dst = (float4*)g_Wv; n4 = 262144; break;
        default: src = Wo; dst = (float4*)g_Wo; n4 = 262144; break;
    }
    int i = blockIdx.x * 256 + threadIdx.x;
    if (i < n4) {
        float4 v = src[i];
        v.x = rtf(v.x); v.y = rtf(v.y); v.z = rtf(v.z); v.w = rtf(v.w);
        dst[i] = v;
    }
}

// ---------------- V transpose ------------------------------------------------
__global__ __launch_bounds__(256) void transposeV_kernel() {
    __shared__ float t[32][33];
    const int tx = threadIdx.x & 31, ty = threadIdx.x >> 5;
    const int bx = blockIdx.x, by = blockIdx.y;
#pragma unroll
    for (int j = 0; j < 4; j++)
        t[ty + j * 8][tx] = g_V[(size_t)(by * 32 + ty + j * 8) * D_MODEL + bx * 32 + tx];
    __syncthreads();
#pragma unroll
    for (int j = 0; j < 4; j++)
        g_Vt[(size_t)(bx * 32 + ty + j * 8) * N_SEQ + by * 32 + tx] = t[tx][ty + j * 8];
}

// ---------------- GEMM (R2, proven): C = A @ W^T + bias ----------------------
#define GPAD 36
#define GEMM_SMEM (2 * 2 * 128 * GPAD * 4)

template <bool ROUND>
__device__ __forceinline__ void gemm_body(const float* __restrict__ A, const float* __restrict__ W,
                                          const float* __restrict__ bias, float* __restrict__ C) {
    extern __shared__ uint32_t dsm[];
    const uint32_t sb = (uint32_t)__cvta_generic_to_shared(dsm);
    const int tid = threadIdx.x, warp = tid >> 5, lane = tid & 31;
    const int grp = lane >> 2, four = lane & 3;
    const int wm = warp >> 2, wn = warp & 3;
    const int m0 = blockIdx.x * 128, n0 = blockIdx.y * 128;

    float acc[4][4][4];
#pragma unroll
    for (int mi = 0; mi < 4; mi++)
#pragma unroll
        for (int ni = 0; ni < 4; ni++)
#pragma unroll
            for (int j = 0; j < 4; j++) acc[mi][ni][j] = 0.f;

    const int lr = tid >> 3, lc = (tid & 7) << 2;

#pragma unroll 1
    for (int kt = -1; kt < 32; kt++) {
        if (kt < 31) {
            const int b = (kt + 1) & 1, k0 = (kt + 1) * 32;
#pragma unroll
            for (int i = 0; i < 4; i++) {
                int r = lr + i * 32;
                CP16(sb + (b * 4608 + r * GPAD + lc) * 4,
                     A + (size_t)(m0 + r) * D_MODEL + k0 + lc);
                CP16(sb + (9216 + b * 4608 + r * GPAD + lc) * 4,
                     W + (size_t)(n0 + r) * D_MODEL + k0 + lc);
            }
            CPC;
        }
        if (kt < 0) continue;
        if (kt < 31) { CPW(1); } else { CPW(0); }
        __syncthreads();

        const int b = kt & 1;
        const uint32_t abase0 = sb + (b * 4608 + (wm * 64 + (lane & 15)) * GPAD + ((lane >> 4) << 2)) * 4;
        const uint32_t bbase0 = sb + (9216 + b * 4608 +
                         (wn * 32 + ((lane >> 4) << 3) + (lane & 7)) * GPAD + (((lane >> 3) & 1) << 2)) * 4;
#pragma unroll
        for (int kk = 0; kk < 32; kk += 8) {
            uint32_t a[4][4], bb[2][4];
#pragma unroll
            for (int mi = 0; mi < 4; mi++) ldsm4(a[mi], abase0 + (mi * 16 * GPAD + kk) * 4);
#pragma unroll
            for (int p = 0; p < 2; p++)   ldsm4(bb[p], bbase0 + (p * 16 * GPAD + kk) * 4);
#pragma unroll
            for (int mi = 0; mi < 4; mi++)
#pragma unroll
                for (int ni = 0; ni < 4; ni++)
                    mma_tf32(acc[mi][ni], a[mi], &bb[ni >> 1][(ni & 1) << 1]);
        }
        __syncthreads();
    }

#pragma unroll
    for (int mi = 0; mi < 4; mi++) {
        int r = m0 + wm * 64 + mi * 16 + grp;
#pragma unroll
        for (int ni = 0; ni < 4; ni++) {
            int c = n0 + wn * 32 + ni * 8 + (four << 1);
            float b0 = bias[c], b1 = bias[c + 1];
            float2 v0, v1;
            v0.x = acc[mi][ni][0] + b0; v0.y = acc[mi][ni][1] + b1;
            v1.x = acc[mi][ni][2] + b0; v1.y = acc[mi][ni][3] + b1;
            if (ROUND) { v0.x = rtf(v0.x); v0.y = rtf(v0.y); v1.x = rtf(v1.x); v1.y = rtf(v1.y); }
            *(float2*)(C + (size_t)r * D_MODEL + c)       = v0;
            *(float2*)(C + (size_t)(r + 8) * D_MODEL + c) = v1;
        }
    }
}

__global__ __launch_bounds__(256, 2) void qkv_gemm_kernel(
    const float* __restrict__ bq, const float* __restrict__ bk, const float* __restrict__ bv) {
    const float* W; const float* b; float* C;
    if (blockIdx.z == 0)      { W = g_Wq; b = bq; C = g_Q; }
    else if (blockIdx.z == 1) { W = g_Wk; b = bk; C = g_K; }
    else                      { W = g_Wv; b = bv; C = g_V; }
    gemm_body<true>(g_x, W, b, C);
}

__global__ __launch_bounds__(256, 2) void out_gemm_kernel(
    const float* __restrict__ bo, float* __restrict__ out) {
    gemm_body<false>(g_AO, g_Wo, bo, out);
}

// ---------------- attention v3: 4 warps x 32 q-rows (halved K/V duplication) --
#define APAD 68
#define QS_OFF 0
#define KS_OFF (128 * APAD)
#define VS_OFF (192 * APAD)
#define PS_OFF (256 * APAD)
#define ATTN_SMEM (384 * APAD * 4)

__global__ __launch_bounds__(128, 2) void attn_kernel(const float* __restrict__ dbias) {
    extern __shared__ uint32_t dsm[];
    const uint32_t sb = (uint32_t)__cvta_generic_to_shared(dsm);
    const int h = blockIdx.x, q0 = blockIdx.y * 128;
    const int tid = threadIdx.x, warp = tid >> 5, lane = tid & 31;
    const int grp = lane >> 2, four = lane & 3;
    const int mb = warp * 32;                  // 32 q-rows per warp

    const int qlr = tid >> 4, qlc = (tid & 15) << 2;   // loader: row(0..7)+i*8, col-word

    // stage Q tile (128 rows)
#pragma unroll
    for (int i = 0; i < 16; i++) {
        int r = qlr + i * 8;
        CP16(sb + (QS_OFF + r * APAD + qlc) * 4, g_Q + (size_t)(q0 + r) * D_MODEL + h * 64 + qlc);
    }
    CPC;

    float Of[2][8][4], Or[2][8][4];
#pragma unroll
    for (int mi = 0; mi < 2; mi++)
#pragma unroll
        for (int ni = 0; ni < 8; ni++)
#pragma unroll
            for (int j = 0; j < 4; j++) { Of[mi][ni][j] = 0.f; Or[mi][ni][j] = 0.f; }
    float lsum[2][2] = {{0.f, 0.f}, {0.f, 0.f}};

    const float* brow[2][2];
#pragma unroll
    for (int mi = 0; mi < 2; mi++) {
        brow[mi][0] = dbias + (size_t)(q0 + mb + mi * 16 + grp) * N_SEQ;
        brow[mi][1] = brow[mi][0] + (size_t)8 * N_SEQ;
    }

    // fragment bases (chunk-invariant)
    uint32_t qab[2], pab[2];
#pragma unroll
    for (int mi = 0; mi < 2; mi++) {
        qab[mi] = sb + (QS_OFF + (mb + mi * 16 + (lane & 15)) * APAD + ((lane >> 4) << 2)) * 4;
        pab[mi] = sb + (PS_OFF + (mb + mi * 16 + (lane & 15)) * APAD + ((lane >> 4) << 2)) * 4;
    }
    const uint32_t kbb = sb + (KS_OFF + (((lane >> 4) << 3) + (lane & 7)) * APAD + (((lane >> 3) & 1) << 2)) * 4;
    const uint32_t vbb = sb + (VS_OFF + (((lane >> 4) << 3) + (lane & 7)) * APAD + (((lane >> 3) & 1) << 2)) * 4;

#pragma unroll 1
    for (int kc = 0; kc < 32; kc++) {
        const int key0 = kc * 64;
        __syncthreads();                       // prior chunk fully consumed
#pragma unroll
        for (int i = 0; i < 8; i++) {
            int r = qlr + i * 8;
            CP16(sb + (KS_OFF + r * APAD + qlc) * 4,
                 g_K + (size_t)(key0 + r) * D_MODEL + h * 64 + qlc);
        }
        CPC;
#pragma unroll
        for (int i = 0; i < 8; i++) {
            int r = qlr + i * 8;
            CP16(sb + (VS_OFF + r * APAD + qlc) * 4,
                 g_Vt + (size_t)(h * 64 + r) * N_SEQ + key0 + qlc);
        }
        CPC;
        CPW(1);                                // Q (first iter) + K ready
        __syncthreads();

        // S = Q @ K^T  (32 x 64 per warp)
        float s[2][8][4];
#pragma unroll
        for (int mi = 0; mi < 2; mi++)
#pragma unroll
            for (int ni = 0; ni < 8; ni++)
#pragma unroll
                for (int j = 0; j < 4; j++) s[mi][ni][j] = 0.f;
#pragma unroll
        for (int kk = 0; kk < 64; kk += 8) {
            uint32_t a[2][4], bb[4][4];
#pragma unroll
            for (int mi = 0; mi < 2; mi++) ldsm4(a[mi], qab[mi] + kk * 4);
#pragma unroll
            for (int p = 0; p < 4; p++) ldsm4(bb[p], kbb + (p * 16 * APAD + kk) * 4);
#pragma unroll
            for (int mi = 0; mi < 2; mi++)
#pragma unroll
                for (int ni = 0; ni < 8; ni++)
                    mma_tf32(s[mi][ni], a[mi], &bb[ni >> 1][(ni & 1) << 1]);
        }

        // P = exp(scale*S - bias); stage P (tf32) to smem
#pragma unroll
        for (int mi = 0; mi < 2; mi++) {
#pragma unroll
            for (int ni = 0; ni < 8; ni++) {
                int c = ni * 8 + (four << 1);
                float2 bA = *(const float2*)(brow[mi][0] + key0 + c);
                float2 bB = *(const float2*)(brow[mi][1] + key0 + c);
                float p0 = __expf(fmaf(s[mi][ni][0], ATTN_SCALE, -bA.x));
                float p1 = __expf(fmaf(s[mi][ni][1], ATTN_SCALE, -bA.y));
                float p2 = __expf(fmaf(s[mi][ni][2], ATTN_SCALE, -bB.x));
                float p3 = __expf(fmaf(s[mi][ni][3], ATTN_SCALE, -bB.y));
                lsum[mi][0] += p0 + p1; lsum[mi][1] += p2 + p3;
                uint2 u0; u0.x = f2tf(p0); u0.y = f2tf(p1);
                uint2 u1; u1.x = f2tf(p2); u1.y = f2tf(p3);
                *(uint2*)(dsm + PS_OFF + (mb + mi * 16 + grp) * APAD + c)     = u0;
                *(uint2*)(dsm + PS_OFF + (mb + mi * 16 + grp + 8) * APAD + c) = u1;
            }
        }
        __syncwarp();                          // own-warp P rows visible

        CPW(0);                                // V arrived
        __syncthreads();                       // V visible CTA-wide

        // Or += P @ V
#pragma unroll
        for (int kk = 0; kk < 64; kk += 8) {
            uint32_t a[2][4], bb[4][4];
#pragma unroll
            for (int mi = 0; mi < 2; mi++) ldsm4(a[mi], pab[mi] + kk * 4);
#pragma unroll
            for (int p = 0; p < 4; p++) ldsm4(bb[p], vbb + (p * 16 * APAD + kk) * 4);
#pragma unroll
            for (int mi = 0; mi < 2; mi++)
#pragma unroll
                for (int ni = 0; ni < 8; ni++)
                    mma_tf32(Or[mi][ni], a[mi], &bb[ni >> 1][(ni & 1) << 1]);
        }

        // 256-key block boundary: normalize & accumulate
        if ((kc & 3) == 3) {
#pragma unroll
            for (int mi = 0; mi < 2; mi++) {
                float L0 = lsum[mi][0], L1 = lsum[mi][1];
                L0 += __shfl_xor_sync(0xffffffffu, L0, 1);
                L0 += __shfl_xor_sync(0xffffffffu, L0, 2);
                L1 += __shfl_xor_sync(0xffffffffu, L1, 1);
                L1 += __shfl_xor_sync(0xffffffffu, L1, 2);
                float i0 = 1.0f / L0, i1 = 1.0f / L1;
#pragma unroll
                for (int ni = 0; ni < 8; ni++) {
                    Of[mi][ni][0] += Or[mi][ni][0] * i0;
                    Of[mi][ni][1] += Or[mi][ni][1] * i0;
                    Of[mi][ni][2] += Or[mi][ni][2] * i1;
                    Of[mi][ni][3] += Or[mi][ni][3] * i1;
                    Or[mi][ni][0] = Or[mi][ni][1] = Or[mi][ni][2] = Or[mi][ni][3] = 0.f;
                }
                lsum[mi][0] = 0.f; lsum[mi][1] = 0.f;
            }
        }
    }

    const float r8 = 1.0f / (8.0f + 1e-8f);    // exact normalizer: nb = 8
#pragma unroll
    for (int mi = 0; mi < 2; mi++) {
#pragma unroll
        for (int ni = 0; ni < 8; ni++) {
            int c = h * 64 + ni * 8 + (four << 1);
            float2 v0, v1;
            v0.x = rtf(Of[mi][ni][0] * r8); v0.y = rtf(Of[mi][ni][1] * r8);
            v1.x = rtf(Of[mi][ni][2] * r8); v1.y = rtf(Of[mi][ni][3] * r8);
            *(float2*)(g_AO + (size_t)(q0 + mb + mi * 16 + grp) * D_MODEL + c)     = v0;
            *(float2*)(g_AO + (size_t)(q0 + mb + mi * 16 + grp + 8) * D_MODEL + c) = v1;
        }
    }
}

// ---------------- launch -----------------------------------------------------
extern "C" void kernel_launch(void* const* d_in, const int* in_sizes, int n_in,
                              void* d_out, int out_size) {
    const float* x  = (const float*)d_in[0];
    const float* db = (const float*)d_in[1];
    const float* Wq = (const float*)d_in[2];
    const float* bq = (const float*)d_in[3];
    const float* Wk = (const float*)d_in[4];
    const float* bk = (const float*)d_in[5];
    const float* Wv = (const float*)d_in[6];
    const float* bv = (const float*)d_in[7];
    const float* Wo = (const float*)d_in[8];
    const float* bo = (const float*)d_in[9];
    float* out = (float*)d_out;

    cudaFuncSetAttribute(qkv_gemm_kernel, cudaFuncAttributeMaxDynamicSharedMemorySize, GEMM_SMEM);
    cudaFuncSetAttribute(out_gemm_kernel, cudaFuncAttributeMaxDynamicSharedMemorySize, GEMM_SMEM);
    cudaFuncSetAttribute(attn_kernel,     cudaFuncAttributeMaxDynamicSharedMemorySize, ATTN_SMEM);

    prep_kernel<<<dim3(2048, 5), 256>>>((const float4*)x, (const float4*)Wq,
                                        (const float4*)Wk, (const float4*)Wv,
                                        (const float4*)Wo);
    qkv_gemm_kernel<<<dim3(16, 8, 3), 256, GEMM_SMEM>>>(bq, bk, bv);
    transposeV_kernel<<<dim3(32, 64), 256>>>();
    attn_kernel<<<dim3(16, 16), 128, ATTN_SMEM>>>(db);
    out_gemm_kernel<<<dim3(16, 8), 256, GEMM_SMEM>>>(bo, out);
}